// round 9
// baseline (speedup 1.0000x reference)
#include <cuda_runtime.h>
#include <math.h>

#define EPSf 1e-6f
#define NT 512
#define STR 108   // float4-aligned row stride, 27*tx mod 8 permutation -> conflict-free

// ---- shared memory layout (float offsets) — 27,516 floats = 107.5 KB ----
#define S1O   0        // s1R[i*108+d]   (10800)
#define S2O   10800    // s2R[j*108+d]   (10800)
#define WMO   21600    // w_maxpool^2 [p*100+d] (1000)
#define R1WO  22600    // 1/n1w maxpool [i*10+p] (1000)
#define R2WO  23600    // 1/n2w maxpool [j*10+p] (1000)
#define R1O   24600    // 1/||s1_i||  (100)
#define R2O   24700    // 1/||s2_j||  (100)
#define RSO   24800    // rowsum of cosm per i (100)
#define JMO   24900    // argmax j per i (int) (100)
#define R2FO  25000    // 1/||s2_last * w_full_p|| per p (16)
#define MPO   25016    // maxpool scratch [i*25+tx] (2500)
#define SMEM_FLOATS 27516

// global scratch: 512 problem slots (b*2+dir), 10000 floats each
__device__ float g_cm[512 * 10000];
__device__ float g_att[512 * 10000];

__device__ __forceinline__ float invs(float x) {
    return 1.0f / sqrtf(fmaxf(x, EPSf));
}

__device__ __forceinline__ float2 ffma2(float2 a, float2 b, float2 c) {
    unsigned long long ua = *reinterpret_cast<unsigned long long*>(&a);
    unsigned long long ub = *reinterpret_cast<unsigned long long*>(&b);
    unsigned long long uc = *reinterpret_cast<unsigned long long*>(&c);
    unsigned long long ud;
    asm("fma.rn.f32x2 %0, %1, %2, %3;" : "=l"(ud) : "l"(ua), "l"(ub), "l"(uc));
    return *reinterpret_cast<float2*>(&ud);
}
__device__ __forceinline__ float2 fmul2(float2 a, float2 b) {
    unsigned long long ua = *reinterpret_cast<unsigned long long*>(&a);
    unsigned long long ub = *reinterpret_cast<unsigned long long*>(&b);
    unsigned long long ud;
    asm("mul.rn.f32x2 %0, %1, %2;" : "=l"(ud) : "l"(ua), "l"(ub));
    return *reinterpret_cast<float2*>(&ud);
}

__global__ __launch_bounds__(NT, 2) void matching_kernel(
    const float* __restrict__ s1g, const float* __restrict__ s2g,
    const float* __restrict__ w1, const float* __restrict__ w2,
    const float* __restrict__ w3, const float* __restrict__ w4,
    const float* __restrict__ w5, const float* __restrict__ w6,
    const float* __restrict__ w7, const float* __restrict__ w8,
    float* __restrict__ out)
{
    extern __shared__ float sm[];
    const int b   = blockIdx.x;   // batch 0..255
    const int dir = blockIdx.y;   // 0=fwd, 1=bwd
    const int tid = threadIdx.x;
    const int dOff = dir * 100;
    const int slot = (b * 2 + dir) * 10000;

    float* s1R = sm + S1O;
    float* s2R = sm + S2O;
    float* cmg = g_cm + slot;
    float* atg = g_att + slot;

    const float* wf = dir ? w2 : w1;
    const float* wm = dir ? w4 : w3;
    const float* we = dir ? w6 : w5;
    const float* ws = dir ? w8 : w7;

    // ================= phase 0: wm^2 + s1/s2 slices into smem ===============
    for (int e = tid; e < 1000; e += NT) {
        float a = wm[e]; sm[WMO + e] = a * a;
    }
    for (int e = tid; e < 10000; e += NT) {
        int i = e / 100, d = e - i * 100;
        size_t g = ((size_t)i * 256 + b) * 200 + dOff + d;
        s1R[i * STR + d] = s1g[g];
        s2R[i * STR + d] = s2g[g];
    }
    __syncthreads();

    // ================= phase 1: norms (parallel sub-jobs) ===================
    if (tid < 200) {                        // unweighted 1/||.||
        int idx = tid % 100;
        const float* base = (tid < 100) ? s1R : s2R;
        float2 a = make_float2(0.f, 0.f);
        for (int d = 0; d < 100; d += 2) {
            float2 v = *(const float2*)&base[idx * STR + d];
            a = ffma2(v, v, a);
        }
        sm[(tid < 100 ? R1O : R2O) + idx] = invs(a.x + a.y);
    } else if (tid >= 240 && tid < 250) {   // full's n2 on s2[99] (wf from global)
        int p = tid - 240;
        float acc = 0.f;
        for (int d = 0; d < 100; d++) {
            float v = s2R[99 * STR + d];
            float w = __ldg(&wf[p * 100 + d]);
            acc = fmaf(v * v, w * w, acc);
        }
        sm[R2FO + p] = invs(acc);
    } else if (tid >= 256 && tid < 456) {   // maxpool weighted norms, 5i x 2p tiles
        int t = tid - 256;                  // 0..199
        int which = t / 100;                // 0: s1, 1: s2
        int r = t - which * 100;            // 0..99
        int i0 = (r / 5) * 5;               // 0..95
        int p0 = (r % 5) * 2;               // 0,2,4,6,8
        const float* base = which ? s2R : s1R;
        float2 acc[5][2];
        #pragma unroll
        for (int m = 0; m < 5; m++)
            #pragma unroll
            for (int q = 0; q < 2; q++) acc[m][q] = make_float2(0.f, 0.f);
        for (int d = 0; d < 100; d += 2) {
            float2 wv[2];
            #pragma unroll
            for (int q = 0; q < 2; q++)
                wv[q] = *(const float2*)&sm[WMO + (p0 + q) * 100 + d];
            #pragma unroll
            for (int m = 0; m < 5; m++) {
                float2 v = *(const float2*)&base[(i0 + m) * STR + d];
                float2 sq = fmul2(v, v);
                #pragma unroll
                for (int q = 0; q < 2; q++) acc[m][q] = ffma2(sq, wv[q], acc[m][q]);
            }
        }
        float* dst = sm + (which ? R2WO : R1WO);
        #pragma unroll
        for (int m = 0; m < 5; m++)
            #pragma unroll
            for (int q = 0; q < 2; q++)
                dst[(i0 + m) * 10 + p0 + q] = invs(acc[m][q].x + acc[m][q].y);
    }
    __syncthreads();

    // ============ phase 2: cosm GEMM (500 thr, 5x4 tile) -> global ==========
    if (tid < 500) {
        const int ty = tid / 25;       // 0..19
        const int tx = tid - ty * 25;  // 0..24
        const int i0 = ty * 5;
        float2 acc[5][4];
        #pragma unroll
        for (int m = 0; m < 5; m++)
            #pragma unroll
            for (int n = 0; n < 4; n++) acc[m][n] = make_float2(0.f, 0.f);
        for (int d = 0; d < 100; d += 2) {
            float2 bv[4];
            #pragma unroll
            for (int n = 0; n < 4; n++)
                bv[n] = *(const float2*)&s2R[(tx + 25 * n) * STR + d];
            #pragma unroll
            for (int m = 0; m < 5; m++) {
                float2 a = *(const float2*)&s1R[(i0 + m) * STR + d];
                #pragma unroll
                for (int n = 0; n < 4; n++) acc[m][n] = ffma2(a, bv[n], acc[m][n]);
            }
        }
        #pragma unroll
        for (int m = 0; m < 5; m++) {
            int i = i0 + m;
            float r1 = sm[R1O + i];
            #pragma unroll
            for (int n = 0; n < 4; n++) {
                int j = tx + 25 * n;
                cmg[i * 100 + j] = (acc[m][n].x + acc[m][n].y) * r1 * sm[R2O + j];
            }
        }
    }
    __syncthreads();

    // ================= phase 3: rowsum + argmax (first-max) =================
    if (tid < 100) {
        const float* row = cmg + tid * 100;
        float rs = 0.f, best = -1e30f; int bj = 0;
        #pragma unroll 4
        for (int j = 0; j < 100; j++) {
            float v = row[j];
            rs += v;
            if (v > best) { best = v; bj = j; }
        }
        sm[RSO + tid] = rs;
        reinterpret_cast<int*>(sm)[JMO + tid] = bj;
    }
    __syncthreads();

    // ====== phase 4: maxpool — 10 p-GEMMs, 500 thr, 5x4 tile, f32x2/d ======
    {
        const int ty = tid / 25;       // 0..19
        const int tx = tid - ty * 25;  // 0..24
        const int i0 = ty * 5;
        for (int p = 0; p < 10; p++) {
            if (tid < 500) {
                float2 acc[5][4];
                #pragma unroll
                for (int m = 0; m < 5; m++)
                    #pragma unroll
                    for (int n = 0; n < 4; n++) acc[m][n] = make_float2(0.f, 0.f);
                const float* wp = sm + WMO + p * 100;
                for (int d = 0; d < 100; d += 2) {
                    float2 wv = *(const float2*)&wp[d];
                    float2 bv[4];
                    #pragma unroll
                    for (int n = 0; n < 4; n++)
                        bv[n] = fmul2(*(const float2*)&s2R[(tx + 25 * n) * STR + d], wv);
                    #pragma unroll
                    for (int m = 0; m < 5; m++) {
                        float2 a = *(const float2*)&s1R[(i0 + m) * STR + d];
                        #pragma unroll
                        for (int n = 0; n < 4; n++) acc[m][n] = ffma2(a, bv[n], acc[m][n]);
                    }
                }
                #pragma unroll
                for (int m = 0; m < 5; m++) {
                    int i = i0 + m;
                    float r1 = sm[R1WO + i * 10 + p];
                    float pm = -1e30f;
                    #pragma unroll
                    for (int n = 0; n < 4; n++) {
                        int j = tx + 25 * n;
                        pm = fmaxf(pm, (acc[m][n].x + acc[m][n].y) * r1 * sm[R2WO + j * 10 + p]);
                    }
                    sm[MPO + i * 25 + tx] = pm;
                }
            }
            __syncthreads();
            if (tid < 100) {
                float mv = -1e30f;
                #pragma unroll 5
                for (int k = 0; k < 25; k++)
                    mv = fmaxf(mv, sm[MPO + tid * 25 + k]);
                out[((size_t)tid * 256 + b) * 80 + 20 + dir * 10 + p] = mv;
            }
            __syncthreads();
        }
    }

    // ====== phase 5: mean attention GEMM (500 thr, 5x4, f32x2/j) -> g_att ==
    if (tid < 500) {
        const int ty = tid / 25;
        const int tx = tid - ty * 25;
        const int i0 = ty * 5;
        float2 acc[5][4];
        #pragma unroll
        for (int m = 0; m < 5; m++)
            #pragma unroll
            for (int n = 0; n < 4; n++) acc[m][n] = make_float2(0.f, 0.f);
        for (int j = 0; j < 100; j += 2) {
            float2 bv[4];
            #pragma unroll
            for (int n = 0; n < 4; n++) {
                int dc = tx + 25 * n;
                bv[n] = make_float2(s2R[j * STR + dc], s2R[(j + 1) * STR + dc]);
            }
            #pragma unroll
            for (int m = 0; m < 5; m++) {
                float2 a = *(const float2*)&cmg[(i0 + m) * 100 + j];
                #pragma unroll
                for (int n = 0; n < 4; n++) acc[m][n] = ffma2(a, bv[n], acc[m][n]);
            }
        }
        #pragma unroll
        for (int m = 0; m < 5; m++) {
            int i = i0 + m;
            float rd = 1.0f / (sm[RSO + i] + EPSf);
            #pragma unroll
            for (int n = 0; n < 4; n++) {
                int d = tx + 25 * n;
                atg[i * 100 + d] = (acc[m][n].x + acc[m][n].y) * rd;
            }
        }
    }
    __syncthreads();

    // ======== phase 6: features — full, mean-att, (dir==1) slot4 ===========
    for (int r = 0; r < 2; r++) {
        int task = tid + NT * r;
        if (task < 1000) {
            int i = task / 10, p = task - i * 10;
            const float* wfp = wf + p * 100;
            const float* wep = we + p * 100;
            const float* wsp = ws + p * 100;
            float numF = 0.f, n1F = 0.f;
            float numE = 0.f, n1E = 0.f, n2E = 0.f;
            float numS = 0.f, n1S = 0.f, n2S = 0.f;
            for (int d = 0; d < 100; d++) {
                float v1 = s1R[i * STR + d];
                float v2l = s2R[99 * STR + d];
                float av = atg[i * 100 + d];
                float wfv = __ldg(&wfp[d]); float wf2 = wfv * wfv;
                float wev = __ldg(&wep[d]); float we2 = wev * wev;
                numF = fmaf(v1 * v2l, wf2, numF);
                n1F  = fmaf(v1 * v1,  wf2, n1F);
                numE = fmaf(v1 * av,  we2, numE);
                n1E  = fmaf(v1 * v1,  we2, n1E);
                n2E  = fmaf(av * av,  we2, n2E);
                if (dir == 1) {
                    float wsv = __ldg(&wsp[d]); float ws2 = wsv * wsv;
                    numS = fmaf(v1 * av, ws2, numS);
                    n1S  = fmaf(v1 * v1, ws2, n1S);
                    n2S  = fmaf(av * av, ws2, n2S);
                }
            }
            size_t ob = ((size_t)i * 256 + b) * 80 + dir * 10 + p;
            out[ob +  0] = numF * invs(n1F) * sm[R2FO + p];
            out[ob + 40] = numE * invs(n1E) * invs(n2E);
            if (dir == 1)
                out[ob + 60] = numS * invs(n1S) * invs(n2S);
        }
    }

    // ======== phase 7 (dir==0 only): max-att features (ref bug kept) =======
    // att vector = s2[seq=0, batch=jmax, fwd slice] read straight from global
    if (dir == 0) {
        for (int r = 0; r < 2; r++) {
            int task = tid + NT * r;
            if (task < 1000) {
                int i = task / 10, p = task - i * 10;
                int jm = reinterpret_cast<int*>(sm)[JMO + i];
                const float* av_row = s2g + (size_t)jm * 200;
                const float* wsp = ws + p * 100;
                float num = 0.f, n1 = 0.f, n2 = 0.f;
                for (int d = 0; d < 100; d++) {
                    float v1 = s1R[i * STR + d];
                    float av = __ldg(&av_row[d]);
                    float wsv = __ldg(&wsp[d]); float ws2 = wsv * wsv;
                    num = fmaf(v1 * av, ws2, num);
                    n1  = fmaf(v1 * v1, ws2, n1);
                    n2  = fmaf(av * av, ws2, n2);
                }
                out[((size_t)i * 256 + b) * 80 + 60 + p] = num * invs(n1) * invs(n2);
            }
        }
    }
}

extern "C" void kernel_launch(void* const* d_in, const int* in_sizes, int n_in,
                              void* d_out, int out_size) {
    const float* s1 = (const float*)d_in[0];
    const float* s2 = (const float*)d_in[1];
    const float* w1 = (const float*)d_in[2];
    const float* w2 = (const float*)d_in[3];
    const float* w3 = (const float*)d_in[4];
    const float* w4 = (const float*)d_in[5];
    const float* w5 = (const float*)d_in[6];
    const float* w6 = (const float*)d_in[7];
    const float* w7 = (const float*)d_in[8];
    const float* w8 = (const float*)d_in[9];
    float* out = (float*)d_out;

    static bool attr_set = false;
    if (!attr_set) {
        cudaFuncSetAttribute(matching_kernel,
                             cudaFuncAttributeMaxDynamicSharedMemorySize,
                             SMEM_FLOATS * (int)sizeof(float));
        attr_set = true;
    }
    dim3 grid(256, 2);
    matching_kernel<<<grid, NT, SMEM_FLOATS * sizeof(float)>>>(
        s1, s2, w1, w2, w3, w4, w5, w6, w7, w8, out);
}

// round 10
// speedup vs baseline: 1.7745x; 1.7745x over previous
#include <cuda_runtime.h>
#include <math.h>

#define EPSf 1e-6f
#define NT 256
#define STR 108   // float4-aligned row stride; 27*tx mod 8 permutation -> conflict-free

// ---- shared memory layout (float offsets) — 26,866 floats = 105 KB ----
#define S1O   0        // s1R[ii*108+d]  local 50 rows (5400)
#define S2O   5400     // s2R[j*108+d]   100 rows (10800)
#define CMO   16200    // cm[ii*108+j] (5400) — reused as att[ii*108+d] after phase 5
#define WMO   21600    // w_maxpool^2 [p*100+d] (1000)
#define R1WO  22600    // 1/n1w [ii*10+p] (500)
#define R2WO  23100    // 1/n2w [j*10+p] (1000)
#define R1O   24100    // 1/||s1_ii|| (50)
#define R2O   24150    // 1/||s2_j|| (100)
#define RSO   24250    // rowsum per ii (50)
#define JMO   24300    // argmax j per ii (int) (50)
#define R2FO  24350    // full n2 per p (16)
#define MPO   24366    // maxpool scratch 2 groups [grp*1250 + ii*25 + tx] (2500)
#define SMEM_FLOATS 26866

__device__ __forceinline__ float invs(float x) {
    return 1.0f / sqrtf(fmaxf(x, EPSf));
}

__device__ __forceinline__ float2 ffma2(float2 a, float2 b, float2 c) {
    unsigned long long ua = *reinterpret_cast<unsigned long long*>(&a);
    unsigned long long ub = *reinterpret_cast<unsigned long long*>(&b);
    unsigned long long uc = *reinterpret_cast<unsigned long long*>(&c);
    unsigned long long ud;
    asm("fma.rn.f32x2 %0, %1, %2, %3;" : "=l"(ud) : "l"(ua), "l"(ub), "l"(uc));
    return *reinterpret_cast<float2*>(&ud);
}
__device__ __forceinline__ float2 fmul2(float2 a, float2 b) {
    unsigned long long ua = *reinterpret_cast<unsigned long long*>(&a);
    unsigned long long ub = *reinterpret_cast<unsigned long long*>(&b);
    unsigned long long ud;
    asm("mul.rn.f32x2 %0, %1, %2;" : "=l"(ud) : "l"(ua), "l"(ub));
    return *reinterpret_cast<float2*>(&ud);
}

__global__ __launch_bounds__(NT, 2) void matching_kernel(
    const float* __restrict__ s1g, const float* __restrict__ s2g,
    const float* __restrict__ w1, const float* __restrict__ w2,
    const float* __restrict__ w3, const float* __restrict__ w4,
    const float* __restrict__ w5, const float* __restrict__ w6,
    const float* __restrict__ w7, const float* __restrict__ w8,
    float* __restrict__ out)
{
    extern __shared__ float sm[];
    const int b   = blockIdx.x;        // batch 0..255
    const int dir = blockIdx.y;        // 0=fwd, 1=bwd
    const int ib  = blockIdx.z * 50;   // i half: global rows [ib, ib+50)
    const int tid = threadIdx.x;
    const int dOff = dir * 100;

    float* s1R = sm + S1O;
    float* s2R = sm + S2O;
    float* cm  = sm + CMO;             // cm during phases 2-5, att afterwards

    const float* wf = dir ? w2 : w1;
    const float* wm = dir ? w4 : w3;
    const float* we = dir ? w6 : w5;
    const float* ws = dir ? w8 : w7;

    // ================= phase 0: wm^2 + s1 half + s2 full into smem ==========
    for (int e = tid; e < 1000; e += NT) {
        float a = wm[e]; sm[WMO + e] = a * a;
    }
    for (int e = tid; e < 5000; e += NT) {
        int ii = e / 100, d = e - ii * 100;
        s1R[ii * STR + d] = s1g[((size_t)(ib + ii) * 256 + b) * 200 + dOff + d];
    }
    for (int e = tid; e < 10000; e += NT) {
        int j = e / 100, d = e - j * 100;
        s2R[j * STR + d] = s2g[((size_t)j * 256 + b) * 200 + dOff + d];
    }
    __syncthreads();

    // ================= phase 1: norms (parallel sub-jobs) ===================
    if (tid < 50) {                          // 1/||s1_ii||
        float2 a = make_float2(0.f, 0.f);
        for (int d = 0; d < 100; d += 2) {
            float2 v = *(const float2*)&s1R[tid * STR + d];
            a = ffma2(v, v, a);
        }
        sm[R1O + tid] = invs(a.x + a.y);
    } else if (tid < 150) {                  // 1/||s2_j||
        int j = tid - 50;
        float2 a = make_float2(0.f, 0.f);
        for (int d = 0; d < 100; d += 2) {
            float2 v = *(const float2*)&s2R[j * STR + d];
            a = ffma2(v, v, a);
        }
        sm[R2O + j] = invs(a.x + a.y);
    } else if (tid < 160) {                  // full's n2 on s2[99] per p
        int p = tid - 150;
        float acc = 0.f;
        for (int d = 0; d < 100; d++) {
            float v = s2R[99 * STR + d];
            float w = __ldg(&wf[p * 100 + d]);
            acc = fmaf(v * v, w * w, acc);
        }
        sm[R2FO + p] = invs(acc);
    } else if (tid < 220) {                  // weighted norms as 5x5 tiles
        int t = tid - 160;                   // 0..59 : 0..19 s1 (50 rows), 20..59 s2 (100 rows)
        int which = (t >= 20);
        int r = which ? (t - 20) : t;
        int i0 = (r / 2) * 5;
        int p0 = (r % 2) * 5;
        const float* base = which ? s2R : s1R;
        float2 acc[5][5];
        #pragma unroll
        for (int m = 0; m < 5; m++)
            #pragma unroll
            for (int q = 0; q < 5; q++) acc[m][q] = make_float2(0.f, 0.f);
        for (int d = 0; d < 100; d += 2) {
            float2 wv[5];
            #pragma unroll
            for (int q = 0; q < 5; q++)
                wv[q] = *(const float2*)&sm[WMO + (p0 + q) * 100 + d];
            #pragma unroll
            for (int m = 0; m < 5; m++) {
                float2 v = *(const float2*)&base[(i0 + m) * STR + d];
                float2 sq = fmul2(v, v);
                #pragma unroll
                for (int q = 0; q < 5; q++) acc[m][q] = ffma2(sq, wv[q], acc[m][q]);
            }
        }
        float* dst = sm + (which ? R2WO : R1WO);
        #pragma unroll
        for (int m = 0; m < 5; m++)
            #pragma unroll
            for (int q = 0; q < 5; q++)
                dst[(i0 + m) * 10 + p0 + q] = invs(acc[m][q].x + acc[m][q].y);
    }
    __syncthreads();

    // ====== phase 2: cosm GEMM (125 thr, 10x4 tile, float4 over d) ==========
    if (tid < 125) {
        const int ty = tid / 25;       // 0..4
        const int tx = tid - ty * 25;  // 0..24
        const int i0 = ty * 10;
        float2 acc[10][4];
        #pragma unroll
        for (int m = 0; m < 10; m++)
            #pragma unroll
            for (int n = 0; n < 4; n++) acc[m][n] = make_float2(0.f, 0.f);
        for (int d = 0; d < 100; d += 4) {
            float4 bv[4];
            #pragma unroll
            for (int n = 0; n < 4; n++)
                bv[n] = *(const float4*)&s2R[(tx + 25 * n) * STR + d];
            #pragma unroll
            for (int m = 0; m < 10; m++) {
                float4 a = *(const float4*)&s1R[(i0 + m) * STR + d];
                float2 alo = make_float2(a.x, a.y), ahi = make_float2(a.z, a.w);
                #pragma unroll
                for (int n = 0; n < 4; n++) {
                    acc[m][n] = ffma2(alo, make_float2(bv[n].x, bv[n].y), acc[m][n]);
                    acc[m][n] = ffma2(ahi, make_float2(bv[n].z, bv[n].w), acc[m][n]);
                }
            }
        }
        #pragma unroll
        for (int m = 0; m < 10; m++) {
            int ii = i0 + m;
            float r1 = sm[R1O + ii];
            #pragma unroll
            for (int n = 0; n < 4; n++) {
                int j = tx + 25 * n;
                cm[ii * STR + j] = (acc[m][n].x + acc[m][n].y) * r1 * sm[R2O + j];
            }
        }
    }
    __syncthreads();

    // ================= phase 3: rowsum + argmax (first-max) =================
    if (tid < 50) {
        float rs = 0.f, best = -1e30f; int bj = 0;
        for (int j = 0; j < 100; j++) {
            float v = cm[tid * STR + j];
            rs += v;
            if (v > best) { best = v; bj = j; }
        }
        sm[RSO + tid] = rs;
        reinterpret_cast<int*>(sm)[JMO + tid] = bj;
    }
    __syncthreads();

    // ====== phase 4: maxpool — 2 grp x 5 p, 10x4 tile, float4 over d ========
    {
        const int grp = tid / 125;         // 0 or 1 (tid>=250 idle)
        const int t   = tid - grp * 125;   // 0..124
        const int ty  = t / 25;            // 0..4
        const int tx  = t - ty * 25;       // 0..24
        const int i0  = ty * 10;
        for (int pi = 0; pi < 5; pi++) {
            if (tid < 250) {
                const int p = grp * 5 + pi;
                float2 acc[10][4];
                #pragma unroll
                for (int m = 0; m < 10; m++)
                    #pragma unroll
                    for (int n = 0; n < 4; n++) acc[m][n] = make_float2(0.f, 0.f);
                const float* wp = sm + WMO + p * 100;
                for (int d = 0; d < 100; d += 4) {
                    float4 wv4 = *(const float4*)&wp[d];
                    float2 wlo = make_float2(wv4.x, wv4.y), whi = make_float2(wv4.z, wv4.w);
                    float2 blo[4], bhi[4];
                    #pragma unroll
                    for (int n = 0; n < 4; n++) {
                        float4 bv = *(const float4*)&s2R[(tx + 25 * n) * STR + d];
                        blo[n] = fmul2(make_float2(bv.x, bv.y), wlo);
                        bhi[n] = fmul2(make_float2(bv.z, bv.w), whi);
                    }
                    #pragma unroll
                    for (int m = 0; m < 10; m++) {
                        float4 a = *(const float4*)&s1R[(i0 + m) * STR + d];
                        float2 alo = make_float2(a.x, a.y), ahi = make_float2(a.z, a.w);
                        #pragma unroll
                        for (int n = 0; n < 4; n++) {
                            acc[m][n] = ffma2(alo, blo[n], acc[m][n]);
                            acc[m][n] = ffma2(ahi, bhi[n], acc[m][n]);
                        }
                    }
                }
                #pragma unroll
                for (int m = 0; m < 10; m++) {
                    int ii = i0 + m;
                    float r1 = sm[R1WO + ii * 10 + p];
                    float pm = -1e30f;
                    #pragma unroll
                    for (int n = 0; n < 4; n++) {
                        int j = tx + 25 * n;
                        pm = fmaxf(pm, (acc[m][n].x + acc[m][n].y) * r1 * sm[R2WO + j * 10 + p]);
                    }
                    sm[MPO + grp * 1250 + ii * 25 + tx] = pm;
                }
            }
            __syncthreads();
            if (tid < 100) {
                int g = tid / 50, ii = tid - g * 50;
                float mv = -1e30f;
                #pragma unroll 5
                for (int k = 0; k < 25; k++)
                    mv = fmaxf(mv, sm[MPO + g * 1250 + ii * 25 + k]);
                out[((size_t)(ib + ii) * 256 + b) * 80 + 20 + dir * 10 + (g * 5 + pi)] = mv;
            }
            __syncthreads();
        }
    }

    // ====== phase 5: mean attention GEMM (125 thr, 10x4, float4 over j) ====
    // att held in regs, then written over the cm buffer after a sync.
    float attv[10][4];
    const int ty5 = tid / 25, tx5 = tid - ty5 * 25, i05 = ty5 * 10;
    if (tid < 125) {
        float2 acc[10][4];
        #pragma unroll
        for (int m = 0; m < 10; m++)
            #pragma unroll
            for (int n = 0; n < 4; n++) acc[m][n] = make_float2(0.f, 0.f);
        for (int j = 0; j < 100; j += 4) {
            float2 blo[4], bhi[4];
            #pragma unroll
            for (int n = 0; n < 4; n++) {
                int dc = tx5 + 25 * n;
                blo[n] = make_float2(s2R[j * STR + dc],       s2R[(j + 1) * STR + dc]);
                bhi[n] = make_float2(s2R[(j + 2) * STR + dc], s2R[(j + 3) * STR + dc]);
            }
            #pragma unroll
            for (int m = 0; m < 10; m++) {
                float4 a = *(const float4*)&cm[(i05 + m) * STR + j];
                float2 alo = make_float2(a.x, a.y), ahi = make_float2(a.z, a.w);
                #pragma unroll
                for (int n = 0; n < 4; n++) {
                    acc[m][n] = ffma2(alo, blo[n], acc[m][n]);
                    acc[m][n] = ffma2(ahi, bhi[n], acc[m][n]);
                }
            }
        }
        #pragma unroll
        for (int m = 0; m < 10; m++) {
            float rd = 1.0f / (sm[RSO + i05 + m] + EPSf);
            #pragma unroll
            for (int n = 0; n < 4; n++)
                attv[m][n] = (acc[m][n].x + acc[m][n].y) * rd;
        }
    }
    __syncthreads();            // all cm reads done
    if (tid < 125) {
        #pragma unroll
        for (int m = 0; m < 10; m++)
            #pragma unroll
            for (int n = 0; n < 4; n++)
                cm[(i05 + m) * STR + tx5 + 25 * n] = attv[m][n];   // cm now holds att
    }
    __syncthreads();
    float* attS = cm;

    // ======== phase 6: features — full, mean-att, (dir==1) slot4 ===========
    for (int r = 0; r < 2; r++) {
        int task = tid + NT * r;
        if (task < 500) {
            int ii = task / 10, p = task - ii * 10;
            const float* wfp = wf + p * 100;
            const float* wep = we + p * 100;
            const float* wsp = ws + p * 100;
            float numF = 0.f, n1F = 0.f;
            float numE = 0.f, n1E = 0.f, n2E = 0.f;
            float numS = 0.f, n1S = 0.f, n2S = 0.f;
            for (int d = 0; d < 100; d++) {
                float v1 = s1R[ii * STR + d];
                float v2l = s2R[99 * STR + d];
                float av = attS[ii * STR + d];
                float wfv = __ldg(&wfp[d]); float wf2 = wfv * wfv;
                float wev = __ldg(&wep[d]); float we2 = wev * wev;
                numF = fmaf(v1 * v2l, wf2, numF);
                n1F  = fmaf(v1 * v1,  wf2, n1F);
                numE = fmaf(v1 * av,  we2, numE);
                n1E  = fmaf(v1 * v1,  we2, n1E);
                n2E  = fmaf(av * av,  we2, n2E);
                if (dir == 1) {
                    float wsv = __ldg(&wsp[d]); float ws2 = wsv * wsv;
                    numS = fmaf(v1 * av, ws2, numS);
                    n1S  = fmaf(v1 * v1, ws2, n1S);
                    n2S  = fmaf(av * av, ws2, n2S);
                }
            }
            size_t ob = ((size_t)(ib + ii) * 256 + b) * 80 + dir * 10 + p;
            out[ob +  0] = numF * invs(n1F) * sm[R2FO + p];
            out[ob + 40] = numE * invs(n1E) * invs(n2E);
            if (dir == 1)
                out[ob + 60] = numS * invs(n1S) * invs(n2S);
        }
    }

    // ======== phase 7 (dir==0 only): max-att features (ref bug kept) =======
    // att vector = s2[seq=0, batch=jmax, fwd slice] read straight from global
    if (dir == 0) {
        for (int r = 0; r < 2; r++) {
            int task = tid + NT * r;
            if (task < 500) {
                int ii = task / 10, p = task - ii * 10;
                int jm = reinterpret_cast<int*>(sm)[JMO + ii];
                const float* av_row = s2g + (size_t)jm * 200;
                const float* wsp = ws + p * 100;
                float num = 0.f, n1 = 0.f, n2 = 0.f;
                for (int d = 0; d < 100; d++) {
                    float v1 = s1R[ii * STR + d];
                    float av = __ldg(&av_row[d]);
                    float wsv = __ldg(&wsp[d]); float ws2 = wsv * wsv;
                    num = fmaf(v1 * av, ws2, num);
                    n1  = fmaf(v1 * v1, ws2, n1);
                    n2  = fmaf(av * av, ws2, n2);
                }
                out[((size_t)(ib + ii) * 256 + b) * 80 + 60 + p] = num * invs(n1) * invs(n2);
            }
        }
    }
}

extern "C" void kernel_launch(void* const* d_in, const int* in_sizes, int n_in,
                              void* d_out, int out_size) {
    const float* s1 = (const float*)d_in[0];
    const float* s2 = (const float*)d_in[1];
    const float* w1 = (const float*)d_in[2];
    const float* w2 = (const float*)d_in[3];
    const float* w3 = (const float*)d_in[4];
    const float* w4 = (const float*)d_in[5];
    const float* w5 = (const float*)d_in[6];
    const float* w6 = (const float*)d_in[7];
    const float* w7 = (const float*)d_in[8];
    const float* w8 = (const float*)d_in[9];
    float* out = (float*)d_out;

    static bool attr_set = false;
    if (!attr_set) {
        cudaFuncSetAttribute(matching_kernel,
                             cudaFuncAttributeMaxDynamicSharedMemorySize,
                             SMEM_FLOATS * (int)sizeof(float));
        attr_set = true;
    }
    dim3 grid(256, 2, 2);
    matching_kernel<<<grid, NT, SMEM_FLOATS * sizeof(float)>>>(
        s1, s2, w1, w2, w3, w4, w5, w6, w7, w8, out);
}